// round 13
// baseline (speedup 1.0000x reference)
#include <cuda_runtime.h>
#include <cuda_bf16.h>

// ---------------- problem constants ----------------
#define Gn 4
#define Sn 2048
#define Dn 2048
#define En 64
#define NTOK (Gn*Sn)                  // 8192 tokens
#define NCOMB ((long long)NTOK*En*63) // 33,030,144 combine elements
#define MCTA 64
#define KC 64
#define KWG 16                        // chunks per warpgroup (2 wgs x 16 x 64 = 2048)
#define K1_THREADS 512
#define GEMM_BLOCKS (NTOK/MCTA)       // 128
#define K1_BLOCKS 148                 // 128 GEMM + 20 dedicated store CTAs
#define ZPC 11                        // zero-fill float4/thread/iteration (GEMM CTAs)
#define ZG ((long long)GEMM_BLOCKS*K1_THREADS*ZPC*KWG)  // 11,534,336 float4
#define SMEM_K1 65536

// ---------------- device scratch ----------------
__device__ float2 g_gate[NTOK];
__device__ int2   g_eidx[NTOK];
__device__ uchar2 g_lpos[NTOK];                 // block-local 0-indexed pos per slot
__device__ int    g_cnt[8*32*En];               // [gk][blk][expert] counts

// swizzled byte offset inside a 64x64-bf16 tile (128B rows, XOR-16B swizzle)
__device__ __forceinline__ unsigned swz(int row, int chunk) {
    return (unsigned)(row*128 + ((chunk ^ (row & 7)) << 4));
}

#define LDSM4(R0_,R1_,R2_,R3_,ADDR) \
  asm volatile("ldmatrix.sync.aligned.m8n8.x4.shared.b16 {%0,%1,%2,%3}, [%4];" \
    : "=r"(R0_),"=r"(R1_),"=r"(R2_),"=r"(R3_) : "r"(ADDR))
#define LDSM4T(R0_,R1_,R2_,R3_,ADDR) \
  asm volatile("ldmatrix.sync.aligned.m8n8.x4.trans.shared.b16 {%0,%1,%2,%3}, [%4];" \
    : "=r"(R0_),"=r"(R1_),"=r"(R2_),"=r"(R3_) : "r"(ADDR))
#define HMMA(C_,A0,A1,A2,A3,B0,B1) \
  asm volatile("mma.sync.aligned.m16n8k16.row.col.f32.bf16.bf16.f32 " \
    "{%0,%1,%2,%3}, {%4,%5,%6,%7}, {%8,%9}, {%0,%1,%2,%3};" \
    : "+f"(C_[0]),"+f"(C_[1]),"+f"(C_[2]),"+f"(C_[3]) \
    : "r"(A0),"r"(A1),"r"(A2),"r"(A3),"r"(B0),"r"(B1))

// ===== K1: zero-fill + dual-warpgroup bf16-split tensor GEMM + softmax/top2 + scan =====
__global__ void __launch_bounds__(K1_THREADS)
k1_fused(const float* __restrict__ x, const float* __restrict__ W,
         const float* __restrict__ b, float* __restrict__ out, long long out_n)
{
    const int tid = threadIdx.x;
    const long long n4 = out_n >> 2;
    float4* o4 = (float4*)out;
    const float4 zz = make_float4(0.f, 0.f, 0.f, 0.f);

    // ---- dedicated store CTAs: drain the tail of the zero-fill, then exit ----
    if (blockIdx.x >= GEMM_BLOCKS) {
        long long idx = (long long)(blockIdx.x - GEMM_BLOCKS)*K1_THREADS + tid;
        for (long long zi = ZG + idx; zi < n4; zi += (long long)(K1_BLOCKS - GEMM_BLOCKS)*K1_THREADS)
            o4[zi] = zz;
        return;
    }

    extern __shared__ __align__(16) unsigned char smx[];   // 64 KB
    const int wg   = tid >> 8;          // warpgroup 0/1 (splits K)
    const int wtid = tid & 255;
    unsigned char* sm = smx + wg*32768;
    const unsigned sb = (unsigned)__cvta_generic_to_shared(sm);
    const unsigned XH = 0, XL = 8192, WHs = 16384, WLs = 24576;

    const int T0   = blockIdx.x * MCTA;
    const int lane = tid & 31;
    const int ww   = (tid >> 5) & 7;    // warp within warpgroup
    const int R0 = (ww & 3) * 16;       // 16 token rows per warp
    const int C0 = (ww >> 2) * 32;      // 32 experts per warp

    const long long zbase = (long long)blockIdx.x*K1_THREADS + tid;
    const long long zstr  = (long long)GEMM_BLOCKS*K1_THREADS;
    if (blockIdx.x == 0 && tid < (int)(out_n & 3LL)) out[n4*4 + tid] = 0.f;

    float acc[4][4];
#pragma unroll
    for (int i = 0; i < 4; ++i)
#pragma unroll
        for (int j = 0; j < 4; ++j) acc[i][j] = 0.f;

    const int dbase = wg * (KWG*KC);    // wg0: 0, wg1: 1024

    // prefetch chunk 0 of this warpgroup
    float2 xv[8], wv[8];
#pragma unroll
    for (int i = 0; i < 8; ++i) {
        int idx = wtid + 256*i;
        int row = idx >> 5, p = idx & 31;
        xv[i] = *(const float2*)(x + (size_t)(T0 + row)*Dn + dbase + 2*p);
        wv[i] = *(const float2*)(W + (size_t)(dbase + row)*En + 2*p);
    }

    const int lm = lane >> 3;
    const int lr = lane & 7;
    const int arow = R0 + ((lm & 1) << 3) + lr;
    const int half = lm >> 1;

    for (int c = 0; c < KWG; ++c) {
        __syncthreads();                      // tiles free
#pragma unroll
        for (int i = 0; i < 8; ++i) {
            int idx = wtid + 256*i;
            int row = idx >> 5, p = idx & 31;
            unsigned off = swz(row, p >> 2) + ((p & 3) << 2);
            __nv_bfloat162 h, l;
            h.x = __float2bfloat16(xv[i].x);
            h.y = __float2bfloat16(xv[i].y);
            l.x = __float2bfloat16(xv[i].x - __bfloat162float(h.x));
            l.y = __float2bfloat16(xv[i].y - __bfloat162float(h.y));
            *(__nv_bfloat162*)(sm + XH + off) = h;
            *(__nv_bfloat162*)(sm + XL + off) = l;
            h.x = __float2bfloat16(wv[i].x);
            h.y = __float2bfloat16(wv[i].y);
            l.x = __float2bfloat16(wv[i].x - __bfloat162float(h.x));
            l.y = __float2bfloat16(wv[i].y - __bfloat162float(h.y));
            *(__nv_bfloat162*)(sm + WHs + off) = h;
            *(__nv_bfloat162*)(sm + WLs + off) = l;
        }
        if (c + 1 < KWG) {
            const int dc0 = dbase + (c + 1)*KC;
#pragma unroll
            for (int i = 0; i < 8; ++i) {
                int idx = wtid + 256*i;
                int row = idx >> 5, p = idx & 31;
                xv[i] = *(const float2*)(x + (size_t)(T0 + row)*Dn + dc0 + 2*p);
                wv[i] = *(const float2*)(W + (size_t)(dc0 + row)*En + 2*p);
            }
        }
        // interleaved zero-fill batch (first ZG float4 of output)
#pragma unroll
        for (int j = 0; j < ZPC; ++j) {
            long long zi = zbase + (long long)(c*ZPC + j)*zstr;
            if (zi < n4) o4[zi] = zz;
        }
        __syncthreads();                      // tiles ready

#pragma unroll
        for (int ks = 0; ks < 4; ++ks) {
            unsigned ah0,ah1,ah2,ah3, al0,al1,al2,al3;
            const unsigned aoff = swz(arow, 2*ks + half);
            LDSM4(ah0,ah1,ah2,ah3, sb + XH + aoff);
            LDSM4(al0,al1,al2,al3, sb + XL + aoff);
            const int krow = 16*ks + ((lm & 1) << 3) + lr;
            unsigned bh[8], bl[8];
            const unsigned boff0 = swz(krow, (C0 >> 3) + half);
            const unsigned boff1 = swz(krow, (C0 >> 3) + 2 + half);
            LDSM4T(bh[0],bh[1],bh[2],bh[3], sb + WHs + boff0);
            LDSM4T(bh[4],bh[5],bh[6],bh[7], sb + WHs + boff1);
            LDSM4T(bl[0],bl[1],bl[2],bl[3], sb + WLs + boff0);
            LDSM4T(bl[4],bl[5],bl[6],bl[7], sb + WLs + boff1);
#pragma unroll
            for (int nt = 0; nt < 4; ++nt) {
                HMMA(acc[nt], ah0,ah1,ah2,ah3, bh[2*nt], bh[2*nt+1]);
                HMMA(acc[nt], ah0,ah1,ah2,ah3, bl[2*nt], bl[2*nt+1]);
                HMMA(acc[nt], al0,al1,al2,al3, bh[2*nt], bh[2*nt+1]);
            }
        }
    }

    // ---- epilogue: wg0 writes partial logits, wg1 accumulates ----
    __syncthreads();                          // all tile reads done; reuse smx
    float* lg = (float*)smx;                  // [64][64] (16 KB)
    unsigned char* se   = smx + 16384;        // [2][64] expert idx per slot
    unsigned char* lpos = smx + 16544;        // [2][64] local position
    int*           cntl = (int*)(smx + 16768);// [2][64] per-expert counts
    {
        const int g = lane >> 2, cc = (lane & 3)*2;
        if (wg == 0) {
#pragma unroll
            for (int nt = 0; nt < 4; ++nt) {
                int e = C0 + nt*8 + cc;
                lg[(R0 + g)*En + e]         = acc[nt][0];
                lg[(R0 + g)*En + e + 1]     = acc[nt][1];
                lg[(R0 + g + 8)*En + e]     = acc[nt][2];
                lg[(R0 + g + 8)*En + e + 1] = acc[nt][3];
            }
        }
        __syncthreads();
        if (wg == 1) {
#pragma unroll
            for (int nt = 0; nt < 4; ++nt) {
                int e = C0 + nt*8 + cc;
                lg[(R0 + g)*En + e]         += acc[nt][0];
                lg[(R0 + g)*En + e + 1]     += acc[nt][1];
                lg[(R0 + g + 8)*En + e]     += acc[nt][2];
                lg[(R0 + g + 8)*En + e + 1] += acc[nt][3];
            }
        }
    }
    __syncthreads();

    // ---- softmax + top2: 16 warps x 4 rows ----
    {
        float2 bb = ((const float2*)b)[lane];
        const int e0 = 2*lane, e1 = 2*lane + 1;
        const int wglob = tid >> 5;           // 0..15
        for (int r = wglob*4; r < wglob*4 + 4; ++r) {
            float2 v = *(float2*)&lg[r*En + 2*lane];
            float l0 = v.x + bb.x, l1 = v.y + bb.y;

            float m = fmaxf(l0, l1);
#pragma unroll
            for (int o = 16; o > 0; o >>= 1) m = fmaxf(m, __shfl_xor_sync(0xffffffffu, m, o));
            float p0 = expf(l0 - m), p1 = expf(l1 - m);
            float s = p0 + p1;
#pragma unroll
            for (int o = 16; o > 0; o >>= 1) s += __shfl_xor_sync(0xffffffffu, s, o);
            p0 = p0 / s;
            p1 = p1 / s;

            float wp; int we;
            if (p1 > p0) { wp = p1; we = e1; } else { wp = p0; we = e0; }
#pragma unroll
            for (int o = 16; o > 0; o >>= 1) {
                float op = __shfl_xor_sync(0xffffffffu, wp, o);
                int   oe = __shfl_xor_sync(0xffffffffu, we, o);
                if (op > wp || (op == wp && oe < we)) { wp = op; we = oe; }
            }
            float a0 = (e0 == we) ? -1.f : p0;
            float a1 = (e1 == we) ? -1.f : p1;
            float wp2; int we2;
            if (a1 > a0) { wp2 = a1; we2 = e1; } else { wp2 = a0; we2 = e0; }
#pragma unroll
            for (int o = 16; o > 0; o >>= 1) {
                float op = __shfl_xor_sync(0xffffffffu, wp2, o);
                int   oe = __shfl_xor_sync(0xffffffffu, we2, o);
                if (op > wp2 || (op == wp2 && oe < we2)) { wp2 = op; we2 = oe; }
            }
            if (lane == 0) {
                g_gate[T0 + r] = make_float2(wp, wp2);
                g_eidx[T0 + r] = make_int2(we, we2);
                se[r]      = (unsigned char)we;
                se[64 + r] = (unsigned char)we2;
            }
        }
    }
    __syncthreads();

    // ---- block-local rank scan for both slots (warps 0 and 1) ----
    if (tid < 128) cntl[tid] = 0;
    __syncthreads();
    if ((tid >> 5) < 2) {
        const int slot = tid >> 5;
#pragma unroll
        for (int it = 0; it < 2; ++it) {
            int t = it*32 + lane;
            int e = se[slot*64 + t];
            unsigned mask = __match_any_sync(0xffffffffu, e);
            int rank = __popc(mask & ((1u << lane) - 1u));
            int base = cntl[slot*64 + e];
            lpos[slot*64 + t] = (unsigned char)(base + rank);
            __syncwarp();
            if (rank == 0) cntl[slot*64 + e] = base + __popc(mask);
            __syncwarp();
        }
    }
    __syncthreads();

    const int gidx = T0 >> 11;              // group = T0 / Sn
    const int blk  = (T0 & (Sn - 1)) >> 6;  // 64-token block within group
    if (tid < 128) {
        int k = tid >> 6, e = tid & 63;
        g_cnt[((gidx*2 + k)*32 + blk)*En + e] = cntl[k*64 + e];
    }
    if (tid < 64)
        g_lpos[T0 + tid] = make_uchar2(lpos[tid], lpos[64 + tid]);
}

// ===== K3: 256 CTAs (one per 64-token block x slot): prefix + scatter =====
__global__ void __launch_bounds__(128)
k3_scatter(float* __restrict__ out, long long out_n,
           const int* __restrict__ capp, int has_mask)
{
    __shared__ int scnt[31*En];   // counts of preceding blocks
    __shared__ int base[En];

    const int gk  = blockIdx.x >> 5;        // 0..7  (group*2 + slot)
    const int blk = blockIdx.x & 31;        // 0..31 (64-token block)
    const int g = gk >> 1, k = gk & 1;
    const int tid = threadIdx.x;
    int cap = 64;
    if (capp) { cap = capp[0]; if (cap > 64) cap = 64; }

    // stage counts of blocks [0, blk) via coalesced loads
    for (int i = tid; i < blk*En; i += 128)
        scnt[i] = g_cnt[gk*32*En + i];
    __syncthreads();

    // per-expert prefix over preceding blocks (LDS chain, conflict-free)
    if (tid < En) {
        int acc = 0;
        for (int bq = 0; bq < blk; ++bq) acc += scnt[bq*En + tid];
        base[tid] = acc;
    }
    __syncthreads();

    // scatter this block's 64 tokens x 2 slots? -- this CTA owns ONE slot (k)
    if (tid < 64) {
        int sl = blk*64 + tid;               // position within group
        int t  = g*Sn + sl;
        int2   ei = g_eidx[t];
        float2 gg = g_gate[t];
        uchar2 lp = g_lpos[t];
        int   e    = k ? ei.y : ei.x;
        float gate = k ? gg.y : gg.x;
        int   pos0 = base[e] + (int)(k ? lp.y : lp.x);
        if (pos0 + 1 < cap) {
            long long off = ((long long)t*En + e)*63 + pos0;
            if (off < out_n) out[off] = gate;
            if (has_mask) {
                long long moff = NCOMB + off;
                if (moff < out_n) out[moff] = (gate != 0.f) ? 1.f : 0.f;
            }
        }
    }
}

// ================= launch =================
extern "C" void kernel_launch(void* const* d_in, const int* in_sizes, int n_in,
                              void* d_out, int out_size)
{
    const float* x = (const float*)d_in[0];
    const float* W = (const float*)d_in[1];
    const float* b = (const float*)d_in[2];
    const int* capp = (n_in >= 4) ? (const int*)d_in[3] : nullptr;
    float* out = (float*)d_out;
    long long out_n = (long long)out_size;
    int has_mask = (out_n >= 2LL*NCOMB) ? 1 : 0;

    cudaFuncSetAttribute(k1_fused, cudaFuncAttributeMaxDynamicSharedMemorySize, SMEM_K1);
    k1_fused<<<K1_BLOCKS, K1_THREADS, SMEM_K1>>>(x, W, b, out, out_n);
    k3_scatter<<<256, 128>>>(out, out_n, capp, has_mask);
}

// round 14
// speedup vs baseline: 1.0476x; 1.0476x over previous
#include <cuda_runtime.h>
#include <cuda_bf16.h>

// ---------------- problem constants ----------------
#define Gn 4
#define Sn 2048
#define Dn 2048
#define En 64
#define NTOK (Gn*Sn)                  // 8192 tokens
#define NCOMB ((long long)NTOK*En*63) // 33,030,144 combine elements
#define MCTA 64
#define KC 64
#define KWG 16                        // chunks per warpgroup (2 wgs x 16 x 64 = 2048)
#define K1_THREADS 512
#define GEMM_BLOCKS (NTOK/MCTA)       // 128
#define K1_BLOCKS 148                 // 128 GEMM + 20 dedicated store CTAs
#define ZPC8 6                        // zero-fill float8/thread/chunk (GEMM CTAs)
#define ZG8 ((long long)GEMM_BLOCKS*K1_THREADS*ZPC8*KWG)  // 6,291,456 float8 (same bytes as R8)
#define SMEM_K1 65536

// ---------------- device scratch ----------------
__device__ float2 g_gate[NTOK];
__device__ int2   g_eidx[NTOK];
__device__ uchar2 g_lpos[NTOK];                 // block-local 0-indexed pos per slot
__device__ int    g_cnt[8*32*En];               // [gk][blk][expert] counts

// swizzled byte offset inside a 64x64-bf16 tile (128B rows, XOR-16B swizzle)
__device__ __forceinline__ unsigned swz(int row, int chunk) {
    return (unsigned)(row*128 + ((chunk ^ (row & 7)) << 4));
}

// ---- 256-bit global memory ops (sm_100+) ----
__device__ __forceinline__ void stg256_zero(float* p) {
    asm volatile("st.global.cs.v8.b32 [%0], {%1,%1,%1,%1,%1,%1,%1,%1};"
                 :: "l"(p), "r"(0u) : "memory");
}
__device__ __forceinline__ void ldg256(float* d, const float* p) {
    asm volatile("ld.global.nc.v8.b32 {%0,%1,%2,%3,%4,%5,%6,%7}, [%8];"
                 : "=f"(d[0]), "=f"(d[1]), "=f"(d[2]), "=f"(d[3]),
                   "=f"(d[4]), "=f"(d[5]), "=f"(d[6]), "=f"(d[7])
                 : "l"(p));
}

// bf16 error-free split of 8 floats -> hi/lo packed bf16x2 quads
__device__ __forceinline__ void cvt_split(const float* f, uint4& hi, uint4& lo) {
    unsigned h[4], l[4];
#pragma unroll
    for (int i = 0; i < 4; ++i) {
        float a = f[2*i], c = f[2*i+1];
        asm("cvt.rn.bf16x2.f32 %0, %1, %2;" : "=r"(h[i]) : "f"(c), "f"(a));
        float fa = __uint_as_float(h[i] << 16);            // exact bf16->f32
        float fc = __uint_as_float(h[i] & 0xFFFF0000u);
        float ra = a - fa, rc = c - fc;
        asm("cvt.rn.bf16x2.f32 %0, %1, %2;" : "=r"(l[i]) : "f"(rc), "f"(ra));
    }
    hi = make_uint4(h[0], h[1], h[2], h[3]);
    lo = make_uint4(l[0], l[1], l[2], l[3]);
}

#define LDSM4(R0_,R1_,R2_,R3_,ADDR) \
  asm volatile("ldmatrix.sync.aligned.m8n8.x4.shared.b16 {%0,%1,%2,%3}, [%4];" \
    : "=r"(R0_),"=r"(R1_),"=r"(R2_),"=r"(R3_) : "r"(ADDR))
#define LDSM4T(R0_,R1_,R2_,R3_,ADDR) \
  asm volatile("ldmatrix.sync.aligned.m8n8.x4.trans.shared.b16 {%0,%1,%2,%3}, [%4];" \
    : "=r"(R0_),"=r"(R1_),"=r"(R2_),"=r"(R3_) : "r"(ADDR))
#define HMMA(C_,A0,A1,A2,A3,B0,B1) \
  asm volatile("mma.sync.aligned.m16n8k16.row.col.f32.bf16.bf16.f32 " \
    "{%0,%1,%2,%3}, {%4,%5,%6,%7}, {%8,%9}, {%0,%1,%2,%3};" \
    : "+f"(C_[0]),"+f"(C_[1]),"+f"(C_[2]),"+f"(C_[3]) \
    : "r"(A0),"r"(A1),"r"(A2),"r"(A3),"r"(B0),"r"(B1))

// ===== K1: zero-fill + dual-warpgroup bf16-split tensor GEMM + softmax/top2 + scan =====
__global__ void __launch_bounds__(K1_THREADS)
k1_fused(const float* __restrict__ x, const float* __restrict__ W,
         const float* __restrict__ b, float* __restrict__ out, long long out_n)
{
    const int tid = threadIdx.x;
    const long long n8 = out_n >> 3;

    // ---- dedicated store CTAs: drain the tail of the zero-fill (256-bit), exit ----
    if (blockIdx.x >= GEMM_BLOCKS) {
        long long idx = (long long)(blockIdx.x - GEMM_BLOCKS)*K1_THREADS + tid;
        for (long long zi = ZG8 + idx; zi < n8; zi += (long long)(K1_BLOCKS - GEMM_BLOCKS)*K1_THREADS)
            stg256_zero(out + zi*8);
        return;
    }

    extern __shared__ __align__(16) unsigned char smx[];   // 64 KB
    const int wg   = tid >> 8;          // warpgroup 0/1 (splits K)
    const int wtid = tid & 255;
    unsigned char* sm = smx + wg*32768;
    const unsigned sb = (unsigned)__cvta_generic_to_shared(sm);
    const unsigned XH = 0, XL = 8192, WHs = 16384, WLs = 24576;

    const int T0   = blockIdx.x * MCTA;
    const int lane = tid & 31;
    const int ww   = (tid >> 5) & 7;    // warp within warpgroup
    const int R0 = (ww & 3) * 16;       // 16 token rows per warp
    const int C0 = (ww >> 2) * 32;      // 32 experts per warp

    const long long zbase = (long long)blockIdx.x*K1_THREADS + tid;
    const long long zstr  = (long long)GEMM_BLOCKS*K1_THREADS;
    if (blockIdx.x == 0 && tid < (int)(out_n & 7LL)) out[n8*8 + tid] = 0.f;

    float acc[4][4];
#pragma unroll
    for (int i = 0; i < 4; ++i)
#pragma unroll
        for (int j = 0; j < 4; ++j) acc[i][j] = 0.f;

    const int dbase = wg * (KWG*KC);    // wg0: 0, wg1: 1024

    // prefetch chunk 0 of this warpgroup (256-bit loads; 2 per array per thread)
    float xv[2][8], wv[2][8];
#pragma unroll
    for (int j = 0; j < 2; ++j) {
        int idx = wtid + 256*j;
        int row = idx >> 3, seg = idx & 7;
        ldg256(xv[j], x + (size_t)(T0 + row)*Dn + dbase + seg*8);
        ldg256(wv[j], W + (size_t)(dbase + row)*En + seg*8);
    }

    const int lm = lane >> 3;
    const int lr = lane & 7;
    const int arow = R0 + ((lm & 1) << 3) + lr;
    const int half = lm >> 1;

    for (int c = 0; c < KWG; ++c) {
        __syncthreads();                      // tiles free
        // convert + swizzled STS.128 (same tile layout as before)
#pragma unroll
        for (int j = 0; j < 2; ++j) {
            int idx = wtid + 256*j;
            int row = idx >> 3, seg = idx & 7;
            unsigned off = swz(row, seg);
            uint4 hi, lo;
            cvt_split(xv[j], hi, lo);
            *(uint4*)(sm + XH + off) = hi;
            *(uint4*)(sm + XL + off) = lo;
            cvt_split(wv[j], hi, lo);
            *(uint4*)(sm + WHs + off) = hi;
            *(uint4*)(sm + WLs + off) = lo;
        }
        if (c + 1 < KWG) {
            const int dc0 = dbase + (c + 1)*KC;
#pragma unroll
            for (int j = 0; j < 2; ++j) {
                int idx = wtid + 256*j;
                int row = idx >> 3, seg = idx & 7;
                ldg256(xv[j], x + (size_t)(T0 + row)*Dn + dc0 + seg*8);
                ldg256(wv[j], W + (size_t)(dc0 + row)*En + seg*8);
            }
        }
        // interleaved zero-fill batch (first ZG8 float8 of output), 256-bit
#pragma unroll
        for (int j = 0; j < ZPC8; ++j) {
            long long zi = zbase + (long long)(c*ZPC8 + j)*zstr;
            if (zi < n8) stg256_zero(out + zi*8);
        }
        __syncthreads();                      // tiles ready

#pragma unroll
        for (int ks = 0; ks < 4; ++ks) {
            unsigned ah0,ah1,ah2,ah3, al0,al1,al2,al3;
            const unsigned aoff = swz(arow, 2*ks + half);
            LDSM4(ah0,ah1,ah2,ah3, sb + XH + aoff);
            LDSM4(al0,al1,al2,al3, sb + XL + aoff);
            const int krow = 16*ks + ((lm & 1) << 3) + lr;
            unsigned bh[8], bl[8];
            const unsigned boff0 = swz(krow, (C0 >> 3) + half);
            const unsigned boff1 = swz(krow, (C0 >> 3) + 2 + half);
            LDSM4T(bh[0],bh[1],bh[2],bh[3], sb + WHs + boff0);
            LDSM4T(bh[4],bh[5],bh[6],bh[7], sb + WHs + boff1);
            LDSM4T(bl[0],bl[1],bl[2],bl[3], sb + WLs + boff0);
            LDSM4T(bl[4],bl[5],bl[6],bl[7], sb + WLs + boff1);
#pragma unroll
            for (int nt = 0; nt < 4; ++nt) {
                HMMA(acc[nt], ah0,ah1,ah2,ah3, bh[2*nt], bh[2*nt+1]);
                HMMA(acc[nt], ah0,ah1,ah2,ah3, bl[2*nt], bl[2*nt+1]);
                HMMA(acc[nt], al0,al1,al2,al3, bh[2*nt], bh[2*nt+1]);
            }
        }
    }

    // ---- epilogue: wg0 writes partial logits, wg1 accumulates ----
    __syncthreads();                          // all tile reads done; reuse smx
    float* lg = (float*)smx;                  // [64][64] (16 KB)
    unsigned char* se   = smx + 16384;        // [2][64] expert idx per slot
    unsigned char* lpos = smx + 16544;        // [2][64] local position
    int*           cntl = (int*)(smx + 16768);// [2][64] per-expert counts
    {
        const int g = lane >> 2, cc = (lane & 3)*2;
        if (wg == 0) {
#pragma unroll
            for (int nt = 0; nt < 4; ++nt) {
                int e = C0 + nt*8 + cc;
                lg[(R0 + g)*En + e]         = acc[nt][0];
                lg[(R0 + g)*En + e + 1]     = acc[nt][1];
                lg[(R0 + g + 8)*En + e]     = acc[nt][2];
                lg[(R0 + g + 8)*En + e + 1] = acc[nt][3];
            }
        }
        __syncthreads();
        if (wg == 1) {
#pragma unroll
            for (int nt = 0; nt < 4; ++nt) {
                int e = C0 + nt*8 + cc;
                lg[(R0 + g)*En + e]         += acc[nt][0];
                lg[(R0 + g)*En + e + 1]     += acc[nt][1];
                lg[(R0 + g + 8)*En + e]     += acc[nt][2];
                lg[(R0 + g + 8)*En + e + 1] += acc[nt][3];
            }
        }
    }
    __syncthreads();

    // ---- softmax + top2: 16 warps x 4 rows ----
    {
        float2 bb = ((const float2*)b)[lane];
        const int e0 = 2*lane, e1 = 2*lane + 1;
        const int wglob = tid >> 5;           // 0..15
        for (int r = wglob*4; r < wglob*4 + 4; ++r) {
            float2 v = *(float2*)&lg[r*En + 2*lane];
            float l0 = v.x + bb.x, l1 = v.y + bb.y;

            float m = fmaxf(l0, l1);
#pragma unroll
            for (int o = 16; o > 0; o >>= 1) m = fmaxf(m, __shfl_xor_sync(0xffffffffu, m, o));
            float p0 = expf(l0 - m), p1 = expf(l1 - m);
            float s = p0 + p1;
#pragma unroll
            for (int o = 16; o > 0; o >>= 1) s += __shfl_xor_sync(0xffffffffu, s, o);
            p0 = p0 / s;
            p1 = p1 / s;

            float wp; int we;
            if (p1 > p0) { wp = p1; we = e1; } else { wp = p0; we = e0; }
#pragma unroll
            for (int o = 16; o > 0; o >>= 1) {
                float op = __shfl_xor_sync(0xffffffffu, wp, o);
                int   oe = __shfl_xor_sync(0xffffffffu, we, o);
                if (op > wp || (op == wp && oe < we)) { wp = op; we = oe; }
            }
            float a0 = (e0 == we) ? -1.f : p0;
            float a1 = (e1 == we) ? -1.f : p1;
            float wp2; int we2;
            if (a1 > a0) { wp2 = a1; we2 = e1; } else { wp2 = a0; we2 = e0; }
#pragma unroll
            for (int o = 16; o > 0; o >>= 1) {
                float op = __shfl_xor_sync(0xffffffffu, wp2, o);
                int   oe = __shfl_xor_sync(0xffffffffu, we2, o);
                if (op > wp2 || (op == wp2 && oe < we2)) { wp2 = op; we2 = oe; }
            }
            if (lane == 0) {
                g_gate[T0 + r] = make_float2(wp, wp2);
                g_eidx[T0 + r] = make_int2(we, we2);
                se[r]      = (unsigned char)we;
                se[64 + r] = (unsigned char)we2;
            }
        }
    }
    __syncthreads();

    // ---- block-local rank scan for both slots (warps 0 and 1) ----
    if (tid < 128) cntl[tid] = 0;
    __syncthreads();
    if ((tid >> 5) < 2) {
        const int slot = tid >> 5;
#pragma unroll
        for (int it = 0; it < 2; ++it) {
            int t = it*32 + lane;
            int e = se[slot*64 + t];
            unsigned mask = __match_any_sync(0xffffffffu, e);
            int rank = __popc(mask & ((1u << lane) - 1u));
            int base = cntl[slot*64 + e];
            lpos[slot*64 + t] = (unsigned char)(base + rank);
            __syncwarp();
            if (rank == 0) cntl[slot*64 + e] = base + __popc(mask);
            __syncwarp();
        }
    }
    __syncthreads();

    const int gidx = T0 >> 11;              // group = T0 / Sn
    const int blk  = (T0 & (Sn - 1)) >> 6;  // 64-token block within group
    if (tid < 128) {
        int k = tid >> 6, e = tid & 63;
        g_cnt[((gidx*2 + k)*32 + blk)*En + e] = cntl[k*64 + e];
    }
    if (tid < 64)
        g_lpos[T0 + tid] = make_uchar2(lpos[tid], lpos[64 + tid]);
}

// ===== K3: 64 CTAs: smem-staged per-expert prefix over blocks + scatter =====
__global__ void __launch_bounds__(256)
k3_scatter(float* __restrict__ out, long long out_n,
           const int* __restrict__ capp, int has_mask)
{
    __shared__ int scnt[32*En];   // all 32 block-count vectors for this (g,k)
    __shared__ int base[4][En];

    const int gk = blockIdx.x >> 3, q = blockIdx.x & 7;
    const int g = gk >> 1, k = gk & 1;
    const int tid = threadIdx.x;
    int cap = 64;
    if (capp) { cap = capp[0]; if (cap > 64) cap = 64; }

    // stage counts via coalesced loads
#pragma unroll
    for (int i = 0; i < 8; ++i)
        scnt[tid + 256*i] = g_cnt[gk*32*En + tid + 256*i];
    __syncthreads();

    // per-expert prefix over blocks (LDS chain)
    if (tid < En) {
        int acc = 0;
        const int e = tid;
        const int bend = q*4 + 4;
        for (int bq = 0; bq < bend; ++bq) {
            if (bq >= q*4) base[bq - q*4][e] = acc;
            acc += scnt[bq*En + e];
        }
    }
    __syncthreads();

    int sl = q*256 + tid;          // position within group
    int t  = g*Sn + sl;
    int2   ei = g_eidx[t];
    float2 gg = g_gate[t];
    uchar2 lp = g_lpos[t];
    int   e    = k ? ei.y : ei.x;
    float gate = k ? gg.y : gg.x;
    int   pos0 = base[(sl >> 6) & 3][e] + (int)(k ? lp.y : lp.x);
    if (pos0 + 1 < cap) {
        long long off = ((long long)t*En + e)*63 + pos0;
        if (off < out_n) out[off] = gate;
        if (has_mask) {
            long long moff = NCOMB + off;
            if (moff < out_n) out[moff] = (gate != 0.f) ? 1.f : 0.f;
        }
    }
}

// ================= launch =================
extern "C" void kernel_launch(void* const* d_in, const int* in_sizes, int n_in,
                              void* d_out, int out_size)
{
    const float* x = (const float*)d_in[0];
    const float* W = (const float*)d_in[1];
    const float* b = (const float*)d_in[2];
    const int* capp = (n_in >= 4) ? (const int*)d_in[3] : nullptr;
    float* out = (float*)d_out;
    long long out_n = (long long)out_size;
    int has_mask = (out_n >= 2LL*NCOMB) ? 1 : 0;

    cudaFuncSetAttribute(k1_fused, cudaFuncAttributeMaxDynamicSharedMemorySize, SMEM_K1);
    k1_fused<<<K1_BLOCKS, K1_THREADS, SMEM_K1>>>(x, W, b, out, out_n);
    k3_scatter<<<64, 256>>>(out, out_n, capp, has_mask);
}

// round 15
// speedup vs baseline: 1.1646x; 1.1117x over previous
#include <cuda_runtime.h>
#include <cuda_bf16.h>

// ---------------- problem constants ----------------
#define Gn 4
#define Sn 2048
#define Dn 2048
#define En 64
#define NTOK (Gn*Sn)                  // 8192 tokens
#define NCOMB ((long long)NTOK*En*63) // 33,030,144 combine elements
#define MCTA 64
#define KC 64
#define KWG 16                        // chunks per warpgroup (2 wgs x 16 x 64 = 2048)
#define K1_THREADS 512
#define GEMM_BLOCKS (NTOK/MCTA)       // 128
#define K1_BLOCKS 148                 // 128 GEMM + 20 dedicated store CTAs
#define ZPC8 6                        // zero-fill float8/thread/chunk (GEMM CTAs)
#define ZG8 ((long long)GEMM_BLOCKS*K1_THREADS*ZPC8*KWG)  // 6,291,456 float8 == round-8 bytes
#define SMEM_K1 65536

// ---------------- device scratch ----------------
__device__ float2 g_gate[NTOK];
__device__ int2   g_eidx[NTOK];
__device__ uchar2 g_lpos[NTOK];                 // block-local 0-indexed pos per slot
__device__ int    g_cnt[8*32*En];               // [gk][blk][expert] counts

// swizzled byte offset inside a 64x64-bf16 tile (128B rows, XOR-16B swizzle)
__device__ __forceinline__ unsigned swz(int row, int chunk) {
    return (unsigned)(row*128 + ((chunk ^ (row & 7)) << 4));
}

// 256-bit zero store (sm_100+); no cache hint
__device__ __forceinline__ void stg256_zero(float* p) {
    asm volatile("st.global.v8.b32 [%0], {%1,%1,%1,%1,%1,%1,%1,%1};"
                 :: "l"(p), "r"(0u) : "memory");
}

#define LDSM4(R0_,R1_,R2_,R3_,ADDR) \
  asm volatile("ldmatrix.sync.aligned.m8n8.x4.shared.b16 {%0,%1,%2,%3}, [%4];" \
    : "=r"(R0_),"=r"(R1_),"=r"(R2_),"=r"(R3_) : "r"(ADDR))
#define LDSM4T(R0_,R1_,R2_,R3_,ADDR) \
  asm volatile("ldmatrix.sync.aligned.m8n8.x4.trans.shared.b16 {%0,%1,%2,%3}, [%4];" \
    : "=r"(R0_),"=r"(R1_),"=r"(R2_),"=r"(R3_) : "r"(ADDR))
#define HMMA(C_,A0,A1,A2,A3,B0,B1) \
  asm volatile("mma.sync.aligned.m16n8k16.row.col.f32.bf16.bf16.f32 " \
    "{%0,%1,%2,%3}, {%4,%5,%6,%7}, {%8,%9}, {%0,%1,%2,%3};" \
    : "+f"(C_[0]),"+f"(C_[1]),"+f"(C_[2]),"+f"(C_[3]) \
    : "r"(A0),"r"(A1),"r"(A2),"r"(A3),"r"(B0),"r"(B1))

// ===== K1: zero-fill + dual-warpgroup bf16-split tensor GEMM + softmax/top2 + scan =====
__global__ void __launch_bounds__(K1_THREADS)
k1_fused(const float* __restrict__ x, const float* __restrict__ W,
         const float* __restrict__ b, float* __restrict__ out, long long out_n)
{
    const int tid = threadIdx.x;
    const long long n8 = out_n >> 3;

    // ---- dedicated store CTAs: drain the tail of the zero-fill (256-bit), exit ----
    if (blockIdx.x >= GEMM_BLOCKS) {
        long long idx = (long long)(blockIdx.x - GEMM_BLOCKS)*K1_THREADS + tid;
        for (long long zi = ZG8 + idx; zi < n8; zi += (long long)(K1_BLOCKS - GEMM_BLOCKS)*K1_THREADS)
            stg256_zero(out + zi*8);
        return;
    }

    extern __shared__ __align__(16) unsigned char smx[];   // 64 KB
    const int wg   = tid >> 8;          // warpgroup 0/1 (splits K)
    const int wtid = tid & 255;
    unsigned char* sm = smx + wg*32768;
    const unsigned sb = (unsigned)__cvta_generic_to_shared(sm);
    const unsigned XH = 0, XL = 8192, WHs = 16384, WLs = 24576;

    const int T0   = blockIdx.x * MCTA;
    const int lane = tid & 31;
    const int ww   = (tid >> 5) & 7;    // warp within warpgroup
    const int R0 = (ww & 3) * 16;       // 16 token rows per warp
    const int C0 = (ww >> 2) * 32;      // 32 experts per warp

    const long long zbase = (long long)blockIdx.x*K1_THREADS + tid;  // float8 units
    const long long zstr  = (long long)GEMM_BLOCKS*K1_THREADS;
    if (blockIdx.x == 0 && tid < (int)(out_n & 7LL)) out[n8*8 + tid] = 0.f;

    float acc[4][4];
#pragma unroll
    for (int i = 0; i < 4; ++i)
#pragma unroll
        for (int j = 0; j < 4; ++j) acc[i][j] = 0.f;

    const int dbase = wg * (KWG*KC);    // wg0: 0, wg1: 1024

    // prefetch chunk 0 of this warpgroup (identical to round-8: 8x LDG.64 each)
    float2 xv[8], wv[8];
#pragma unroll
    for (int i = 0; i < 8; ++i) {
        int idx = wtid + 256*i;
        int row = idx >> 5, p = idx & 31;
        xv[i] = *(const float2*)(x + (size_t)(T0 + row)*Dn + dbase + 2*p);
        wv[i] = *(const float2*)(W + (size_t)(dbase + row)*En + 2*p);
    }

    const int lm = lane >> 3;
    const int lr = lane & 7;
    const int arow = R0 + ((lm & 1) << 3) + lr;
    const int half = lm >> 1;

    for (int c = 0; c < KWG; ++c) {
        __syncthreads();                      // tiles free
#pragma unroll
        for (int i = 0; i < 8; ++i) {
            int idx = wtid + 256*i;
            int row = idx >> 5, p = idx & 31;
            unsigned off = swz(row, p >> 2) + ((p & 3) << 2);
            __nv_bfloat162 h, l;
            h.x = __float2bfloat16(xv[i].x);
            h.y = __float2bfloat16(xv[i].y);
            l.x = __float2bfloat16(xv[i].x - __bfloat162float(h.x));
            l.y = __float2bfloat16(xv[i].y - __bfloat162float(h.y));
            *(__nv_bfloat162*)(sm + XH + off) = h;
            *(__nv_bfloat162*)(sm + XL + off) = l;
            h.x = __float2bfloat16(wv[i].x);
            h.y = __float2bfloat16(wv[i].y);
            l.x = __float2bfloat16(wv[i].x - __bfloat162float(h.x));
            l.y = __float2bfloat16(wv[i].y - __bfloat162float(h.y));
            *(__nv_bfloat162*)(sm + WHs + off) = h;
            *(__nv_bfloat162*)(sm + WLs + off) = l;
        }
        if (c + 1 < KWG) {
            const int dc0 = dbase + (c + 1)*KC;
#pragma unroll
            for (int i = 0; i < 8; ++i) {
                int idx = wtid + 256*i;
                int row = idx >> 5, p = idx & 31;
                xv[i] = *(const float2*)(x + (size_t)(T0 + row)*Dn + dc0 + 2*p);
                wv[i] = *(const float2*)(W + (size_t)(dc0 + row)*En + 2*p);
            }
        }
        // interleaved zero-fill batch (first ZG8 float8 of output), 256-bit stores
#pragma unroll
        for (int j = 0; j < ZPC8; ++j) {
            long long zi = zbase + (long long)(c*ZPC8 + j)*zstr;
            if (zi < n8) stg256_zero(out + zi*8);
        }
        __syncthreads();                      // tiles ready

#pragma unroll
        for (int ks = 0; ks < 4; ++ks) {
            unsigned ah0,ah1,ah2,ah3, al0,al1,al2,al3;
            const unsigned aoff = swz(arow, 2*ks + half);
            LDSM4(ah0,ah1,ah2,ah3, sb + XH + aoff);
            LDSM4(al0,al1,al2,al3, sb + XL + aoff);
            const int krow = 16*ks + ((lm & 1) << 3) + lr;
            unsigned bh[8], bl[8];
            const unsigned boff0 = swz(krow, (C0 >> 3) + half);
            const unsigned boff1 = swz(krow, (C0 >> 3) + 2 + half);
            LDSM4T(bh[0],bh[1],bh[2],bh[3], sb + WHs + boff0);
            LDSM4T(bh[4],bh[5],bh[6],bh[7], sb + WHs + boff1);
            LDSM4T(bl[0],bl[1],bl[2],bl[3], sb + WLs + boff0);
            LDSM4T(bl[4],bl[5],bl[6],bl[7], sb + WLs + boff1);
#pragma unroll
            for (int nt = 0; nt < 4; ++nt) {
                HMMA(acc[nt], ah0,ah1,ah2,ah3, bh[2*nt], bh[2*nt+1]);
                HMMA(acc[nt], ah0,ah1,ah2,ah3, bl[2*nt], bl[2*nt+1]);
                HMMA(acc[nt], al0,al1,al2,al3, bh[2*nt], bh[2*nt+1]);
            }
        }
    }

    // ---- epilogue: wg0 writes partial logits, wg1 accumulates ----
    __syncthreads();                          // all tile reads done; reuse smx
    float* lg = (float*)smx;                  // [64][64] (16 KB)
    unsigned char* se   = smx + 16384;        // [2][64] expert idx per slot
    unsigned char* lpos = smx + 16544;        // [2][64] local position
    int*           cntl = (int*)(smx + 16768);// [2][64] per-expert counts
    {
        const int g = lane >> 2, cc = (lane & 3)*2;
        if (wg == 0) {
#pragma unroll
            for (int nt = 0; nt < 4; ++nt) {
                int e = C0 + nt*8 + cc;
                lg[(R0 + g)*En + e]         = acc[nt][0];
                lg[(R0 + g)*En + e + 1]     = acc[nt][1];
                lg[(R0 + g + 8)*En + e]     = acc[nt][2];
                lg[(R0 + g + 8)*En + e + 1] = acc[nt][3];
            }
        }
        __syncthreads();
        if (wg == 1) {
#pragma unroll
            for (int nt = 0; nt < 4; ++nt) {
                int e = C0 + nt*8 + cc;
                lg[(R0 + g)*En + e]         += acc[nt][0];
                lg[(R0 + g)*En + e + 1]     += acc[nt][1];
                lg[(R0 + g + 8)*En + e]     += acc[nt][2];
                lg[(R0 + g + 8)*En + e + 1] += acc[nt][3];
            }
        }
    }
    __syncthreads();

    // ---- softmax + top2: 16 warps x 4 rows ----
    {
        float2 bb = ((const float2*)b)[lane];
        const int e0 = 2*lane, e1 = 2*lane + 1;
        const int wglob = tid >> 5;           // 0..15
        for (int r = wglob*4; r < wglob*4 + 4; ++r) {
            float2 v = *(float2*)&lg[r*En + 2*lane];
            float l0 = v.x + bb.x, l1 = v.y + bb.y;

            float m = fmaxf(l0, l1);
#pragma unroll
            for (int o = 16; o > 0; o >>= 1) m = fmaxf(m, __shfl_xor_sync(0xffffffffu, m, o));
            float p0 = expf(l0 - m), p1 = expf(l1 - m);
            float s = p0 + p1;
#pragma unroll
            for (int o = 16; o > 0; o >>= 1) s += __shfl_xor_sync(0xffffffffu, s, o);
            p0 = p0 / s;
            p1 = p1 / s;

            float wp; int we;
            if (p1 > p0) { wp = p1; we = e1; } else { wp = p0; we = e0; }
#pragma unroll
            for (int o = 16; o > 0; o >>= 1) {
                float op = __shfl_xor_sync(0xffffffffu, wp, o);
                int   oe = __shfl_xor_sync(0xffffffffu, we, o);
                if (op > wp || (op == wp && oe < we)) { wp = op; we = oe; }
            }
            float a0 = (e0 == we) ? -1.f : p0;
            float a1 = (e1 == we) ? -1.f : p1;
            float wp2; int we2;
            if (a1 > a0) { wp2 = a1; we2 = e1; } else { wp2 = a0; we2 = e0; }
#pragma unroll
            for (int o = 16; o > 0; o >>= 1) {
                float op = __shfl_xor_sync(0xffffffffu, wp2, o);
                int   oe = __shfl_xor_sync(0xffffffffu, we2, o);
                if (op > wp2 || (op == wp2 && oe < we2)) { wp2 = op; we2 = oe; }
            }
            if (lane == 0) {
                g_gate[T0 + r] = make_float2(wp, wp2);
                g_eidx[T0 + r] = make_int2(we, we2);
                se[r]      = (unsigned char)we;
                se[64 + r] = (unsigned char)we2;
            }
        }
    }
    __syncthreads();

    // ---- block-local rank scan for both slots (warps 0 and 1) ----
    if (tid < 128) cntl[tid] = 0;
    __syncthreads();
    if ((tid >> 5) < 2) {
        const int slot = tid >> 5;
#pragma unroll
        for (int it = 0; it < 2; ++it) {
            int t = it*32 + lane;
            int e = se[slot*64 + t];
            unsigned mask = __match_any_sync(0xffffffffu, e);
            int rank = __popc(mask & ((1u << lane) - 1u));
            int base = cntl[slot*64 + e];
            lpos[slot*64 + t] = (unsigned char)(base + rank);
            __syncwarp();
            if (rank == 0) cntl[slot*64 + e] = base + __popc(mask);
            __syncwarp();
        }
    }
    __syncthreads();

    const int gidx = T0 >> 11;              // group = T0 / Sn
    const int blk  = (T0 & (Sn - 1)) >> 6;  // 64-token block within group
    if (tid < 128) {
        int k = tid >> 6, e = tid & 63;
        g_cnt[((gidx*2 + k)*32 + blk)*En + e] = cntl[k*64 + e];
    }
    if (tid < 64)
        g_lpos[T0 + tid] = make_uchar2(lpos[tid], lpos[64 + tid]);
}

// ===== K3: 64 CTAs: smem-staged per-expert prefix over blocks + scatter =====
__global__ void __launch_bounds__(256)
k3_scatter(float* __restrict__ out, long long out_n,
           const int* __restrict__ capp, int has_mask)
{
    __shared__ int scnt[32*En];   // all 32 block-count vectors for this (g,k)
    __shared__ int base[4][En];

    const int gk = blockIdx.x >> 3, q = blockIdx.x & 7;
    const int g = gk >> 1, k = gk & 1;
    const int tid = threadIdx.x;
    int cap = 64;
    if (capp) { cap = capp[0]; if (cap > 64) cap = 64; }

    // stage counts via coalesced loads
#pragma unroll
    for (int i = 0; i < 8; ++i)
        scnt[tid + 256*i] = g_cnt[gk*32*En + tid + 256*i];
    __syncthreads();

    // per-expert prefix over blocks (LDS chain)
    if (tid < En) {
        int acc = 0;
        const int e = tid;
        const int bend = q*4 + 4;
        for (int bq = 0; bq < bend; ++bq) {
            if (bq >= q*4) base[bq - q*4][e] = acc;
            acc += scnt[bq*En + e];
        }
    }
    __syncthreads();

    int sl = q*256 + tid;          // position within group
    int t  = g*Sn + sl;
    int2   ei = g_eidx[t];
    float2 gg = g_gate[t];
    uchar2 lp = g_lpos[t];
    int   e    = k ? ei.y : ei.x;
    float gate = k ? gg.y : gg.x;
    int   pos0 = base[(sl >> 6) & 3][e] + (int)(k ? lp.y : lp.x);
    if (pos0 + 1 < cap) {
        long long off = ((long long)t*En + e)*63 + pos0;
        if (off < out_n) out[off] = gate;
        if (has_mask) {
            long long moff = NCOMB + off;
            if (moff < out_n) out[moff] = (gate != 0.f) ? 1.f : 0.f;
        }
    }
}

// ================= launch =================
extern "C" void kernel_launch(void* const* d_in, const int* in_sizes, int n_in,
                              void* d_out, int out_size)
{
    const float* x = (const float*)d_in[0];
    const float* W = (const float*)d_in[1];
    const float* b = (const float*)d_in[2];
    const int* capp = (n_in >= 4) ? (const int*)d_in[3] : nullptr;
    float* out = (float*)d_out;
    long long out_n = (long long)out_size;
    int has_mask = (out_n >= 2LL*NCOMB) ? 1 : 0;

    cudaFuncSetAttribute(k1_fused, cudaFuncAttributeMaxDynamicSharedMemorySize, SMEM_K1);
    k1_fused<<<K1_BLOCKS, K1_THREADS, SMEM_K1>>>(x, W, b, out, out_n);
    k3_scatter<<<64, 256>>>(out, out_n, capp, has_mask);
}

// round 16
// speedup vs baseline: 1.2278x; 1.0543x over previous
#include <cuda_runtime.h>
#include <cuda_bf16.h>

// ---------------- problem constants ----------------
#define Gn 4
#define Sn 2048
#define Dn 2048
#define En 64
#define NTOK (Gn*Sn)                  // 8192 tokens
#define NCOMB ((long long)NTOK*En*63) // 33,030,144 combine elements
#define MCTA 64
#define KC 64
#define KWG 16                        // chunks per warpgroup (2 wgs x 16 x 64 = 2048)
#define K1_THREADS 512
#define GEMM_BLOCKS (NTOK/MCTA)       // 128
#define K1_BLOCKS 148                 // 128 GEMM + 20 TMA-store CTAs
#define ZB 7                          // 16KB bulk-zero stores per chunk (GEMM CTAs)
#define ZBLKG ((long long)GEMM_BLOCKS*KWG*ZB)   // 14336 blocks covered by GEMM CTAs
#define ZBUF 65536                    // smem offset of 16KB zero buffer
#define SMEM_K1 81920

// ---------------- device scratch ----------------
__device__ float2 g_gate[NTOK];
__device__ int2   g_eidx[NTOK];
__device__ uchar2 g_lpos[NTOK];                 // block-local 0-indexed pos per slot
__device__ int    g_cnt[8*32*En];               // [gk][blk][expert] counts

// swizzled byte offset inside a 64x64-bf16 tile (128B rows, XOR-16B swizzle)
__device__ __forceinline__ unsigned swz(int row, int chunk) {
    return (unsigned)(row*128 + ((chunk ^ (row & 7)) << 4));
}

// ---- TMA bulk zero store: smem -> global, 16KB ----
__device__ __forceinline__ void bulk_zero(float* gdst, unsigned s_src) {
    asm volatile("cp.async.bulk.global.shared::cta.bulk_group [%0], [%1], %2;"
                 :: "l"(gdst), "r"(s_src), "r"(16384u) : "memory");
}
#define BULK_COMMIT() asm volatile("cp.async.bulk.commit_group;" ::: "memory")
#define BULK_WAIT0()  asm volatile("cp.async.bulk.wait_group 0;" ::: "memory")
#define FENCE_ASYNC() asm volatile("fence.proxy.async.shared::cta;" ::: "memory")

#define LDSM4(R0_,R1_,R2_,R3_,ADDR) \
  asm volatile("ldmatrix.sync.aligned.m8n8.x4.shared.b16 {%0,%1,%2,%3}, [%4];" \
    : "=r"(R0_),"=r"(R1_),"=r"(R2_),"=r"(R3_) : "r"(ADDR))
#define LDSM4T(R0_,R1_,R2_,R3_,ADDR) \
  asm volatile("ldmatrix.sync.aligned.m8n8.x4.trans.shared.b16 {%0,%1,%2,%3}, [%4];" \
    : "=r"(R0_),"=r"(R1_),"=r"(R2_),"=r"(R3_) : "r"(ADDR))
#define HMMA(C_,A0,A1,A2,A3,B0,B1) \
  asm volatile("mma.sync.aligned.m16n8k16.row.col.f32.bf16.bf16.f32 " \
    "{%0,%1,%2,%3}, {%4,%5,%6,%7}, {%8,%9}, {%0,%1,%2,%3};" \
    : "+f"(C_[0]),"+f"(C_[1]),"+f"(C_[2]),"+f"(C_[3]) \
    : "r"(A0),"r"(A1),"r"(A2),"r"(A3),"r"(B0),"r"(B1))

// ===== K1: TMA zero-fill + dual-warpgroup bf16-split GEMM + softmax/top2 + scan =====
__global__ void __launch_bounds__(K1_THREADS)
k1_fused(const float* __restrict__ x, const float* __restrict__ W,
         const float* __restrict__ b, float* __restrict__ out, long long out_n)
{
    const int tid = threadIdx.x;
    const long long nblk = out_n >> 12;       // 16KB blocks (4096 floats each)
    extern __shared__ __align__(16) unsigned char smx[];

    // ---- dedicated TMA-store CTAs: push the tail blocks via bulk stores, exit ----
    if (blockIdx.x >= GEMM_BLOCKS) {
        for (int i = tid; i < 4096; i += K1_THREADS) ((float*)smx)[i] = 0.f;
        __syncthreads();
        if (tid == 0) {
            FENCE_ASYNC();
            unsigned zsrc = (unsigned)__cvta_generic_to_shared(smx);
            for (long long zi = ZBLKG + (blockIdx.x - GEMM_BLOCKS); zi < nblk;
                 zi += (K1_BLOCKS - GEMM_BLOCKS)) {
                bulk_zero(out + zi*4096, zsrc);
                BULK_COMMIT();
            }
            BULK_WAIT0();
        }
        return;
    }

    const int wg   = tid >> 8;          // warpgroup 0/1 (splits K)
    const int wtid = tid & 255;
    unsigned char* sm = smx + wg*32768;
    const unsigned sb = (unsigned)__cvta_generic_to_shared(sm);
    const unsigned XH = 0, XL = 8192, WHs = 16384, WLs = 24576;

    const int T0   = blockIdx.x * MCTA;
    const int lane = tid & 31;
    const int ww   = (tid >> 5) & 7;    // warp within warpgroup
    const int R0 = (ww & 3) * 16;       // 16 token rows per warp
    const int C0 = (ww >> 2) * 32;      // 32 experts per warp

    // init 16KB zero buffer + scalar tail zeros
    for (int i = tid; i < 4096; i += K1_THREADS) ((float*)(smx + ZBUF))[i] = 0.f;
    if (blockIdx.x == 0)
        for (long long i = nblk*4096 + tid; i < out_n; i += K1_THREADS) out[i] = 0.f;

    float acc[4][4];
#pragma unroll
    for (int i = 0; i < 4; ++i)
#pragma unroll
        for (int j = 0; j < 4; ++j) acc[i][j] = 0.f;

    const int dbase = wg * (KWG*KC);    // wg0: 0, wg1: 1024

    // prefetch chunk 0 of this warpgroup
    float2 xv[8], wv[8];
#pragma unroll
    for (int i = 0; i < 8; ++i) {
        int idx = wtid + 256*i;
        int row = idx >> 5, p = idx & 31;
        xv[i] = *(const float2*)(x + (size_t)(T0 + row)*Dn + dbase + 2*p);
        wv[i] = *(const float2*)(W + (size_t)(dbase + row)*En + 2*p);
    }

    __syncthreads();                          // zero buffer ready
    const unsigned zsrc = (unsigned)__cvta_generic_to_shared(smx + ZBUF);
    if (tid == 0) FENCE_ASYNC();

    const int lm = lane >> 3;
    const int lr = lane & 7;
    const int arow = R0 + ((lm & 1) << 3) + lr;
    const int half = lm >> 1;

    for (int c = 0; c < KWG; ++c) {
        __syncthreads();                      // tiles free
#pragma unroll
        for (int i = 0; i < 8; ++i) {
            int idx = wtid + 256*i;
            int row = idx >> 5, p = idx & 31;
            unsigned off = swz(row, p >> 2) + ((p & 3) << 2);
            __nv_bfloat162 h, l;
            h.x = __float2bfloat16(xv[i].x);
            h.y = __float2bfloat16(xv[i].y);
            l.x = __float2bfloat16(xv[i].x - __bfloat162float(h.x));
            l.y = __float2bfloat16(xv[i].y - __bfloat162float(h.y));
            *(__nv_bfloat162*)(sm + XH + off) = h;
            *(__nv_bfloat162*)(sm + XL + off) = l;
            h.x = __float2bfloat16(wv[i].x);
            h.y = __float2bfloat16(wv[i].y);
            l.x = __float2bfloat16(wv[i].x - __bfloat162float(h.x));
            l.y = __float2bfloat16(wv[i].y - __bfloat162float(h.y));
            *(__nv_bfloat162*)(sm + WHs + off) = h;
            *(__nv_bfloat162*)(sm + WLs + off) = l;
        }
        if (c + 1 < KWG) {
            const int dc0 = dbase + (c + 1)*KC;
#pragma unroll
            for (int i = 0; i < 8; ++i) {
                int idx = wtid + 256*i;
                int row = idx >> 5, p = idx & 31;
                xv[i] = *(const float2*)(x + (size_t)(T0 + row)*Dn + dc0 + 2*p);
                wv[i] = *(const float2*)(W + (size_t)(dc0 + row)*En + 2*p);
            }
        }
        // zero-fill: thread 0 hands 7 x 16KB blocks to the TMA engine
        if (tid == 0) {
#pragma unroll
            for (int j = 0; j < ZB; ++j) {
                long long zi = (long long)blockIdx.x + (long long)(c*ZB + j)*GEMM_BLOCKS;
                if (zi < nblk) bulk_zero(out + zi*4096, zsrc);
            }
            BULK_COMMIT();
        }
        __syncthreads();                      // tiles ready

#pragma unroll
        for (int ks = 0; ks < 4; ++ks) {
            unsigned ah0,ah1,ah2,ah3, al0,al1,al2,al3;
            const unsigned aoff = swz(arow, 2*ks + half);
            LDSM4(ah0,ah1,ah2,ah3, sb + XH + aoff);
            LDSM4(al0,al1,al2,al3, sb + XL + aoff);
            const int krow = 16*ks + ((lm & 1) << 3) + lr;
            unsigned bh[8], bl[8];
            const unsigned boff0 = swz(krow, (C0 >> 3) + half);
            const unsigned boff1 = swz(krow, (C0 >> 3) + 2 + half);
            LDSM4T(bh[0],bh[1],bh[2],bh[3], sb + WHs + boff0);
            LDSM4T(bh[4],bh[5],bh[6],bh[7], sb + WHs + boff1);
            LDSM4T(bl[0],bl[1],bl[2],bl[3], sb + WLs + boff0);
            LDSM4T(bl[4],bl[5],bl[6],bl[7], sb + WLs + boff1);
#pragma unroll
            for (int nt = 0; nt < 4; ++nt) {
                HMMA(acc[nt], ah0,ah1,ah2,ah3, bh[2*nt], bh[2*nt+1]);
                HMMA(acc[nt], ah0,ah1,ah2,ah3, bl[2*nt], bl[2*nt+1]);
                HMMA(acc[nt], al0,al1,al2,al3, bh[2*nt], bh[2*nt+1]);
            }
        }
    }

    if (tid == 0) BULK_WAIT0();               // drain TMA store queue

    // ---- epilogue: wg0 writes partial logits, wg1 accumulates ----
    __syncthreads();                          // all tile reads done; reuse smx
    float* lg = (float*)smx;                  // [64][64] (16 KB)
    unsigned char* se   = smx + 16384;        // [2][64] expert idx per slot
    unsigned char* lpos = smx + 16544;        // [2][64] local position
    int*           cntl = (int*)(smx + 16768);// [2][64] per-expert counts
    {
        const int g = lane >> 2, cc = (lane & 3)*2;
        if (wg == 0) {
#pragma unroll
            for (int nt = 0; nt < 4; ++nt) {
                int e = C0 + nt*8 + cc;
                lg[(R0 + g)*En + e]         = acc[nt][0];
                lg[(R0 + g)*En + e + 1]     = acc[nt][1];
                lg[(R0 + g + 8)*En + e]     = acc[nt][2];
                lg[(R0 + g + 8)*En + e + 1] = acc[nt][3];
            }
        }
        __syncthreads();
        if (wg == 1) {
#pragma unroll
            for (int nt = 0; nt < 4; ++nt) {
                int e = C0 + nt*8 + cc;
                lg[(R0 + g)*En + e]         += acc[nt][0];
                lg[(R0 + g)*En + e + 1]     += acc[nt][1];
                lg[(R0 + g + 8)*En + e]     += acc[nt][2];
                lg[(R0 + g + 8)*En + e + 1] += acc[nt][3];
            }
        }
    }
    __syncthreads();

    // ---- softmax + top2: 16 warps x 4 rows ----
    {
        float2 bb = ((const float2*)b)[lane];
        const int e0 = 2*lane, e1 = 2*lane + 1;
        const int wglob = tid >> 5;           // 0..15
        for (int r = wglob*4; r < wglob*4 + 4; ++r) {
            float2 v = *(float2*)&lg[r*En + 2*lane];
            float l0 = v.x + bb.x, l1 = v.y + bb.y;

            float m = fmaxf(l0, l1);
#pragma unroll
            for (int o = 16; o > 0; o >>= 1) m = fmaxf(m, __shfl_xor_sync(0xffffffffu, m, o));
            float p0 = expf(l0 - m), p1 = expf(l1 - m);
            float s = p0 + p1;
#pragma unroll
            for (int o = 16; o > 0; o >>= 1) s += __shfl_xor_sync(0xffffffffu, s, o);
            p0 = p0 / s;
            p1 = p1 / s;

            float wp; int we;
            if (p1 > p0) { wp = p1; we = e1; } else { wp = p0; we = e0; }
#pragma unroll
            for (int o = 16; o > 0; o >>= 1) {
                float op = __shfl_xor_sync(0xffffffffu, wp, o);
                int   oe = __shfl_xor_sync(0xffffffffu, we, o);
                if (op > wp || (op == wp && oe < we)) { wp = op; we = oe; }
            }
            float a0 = (e0 == we) ? -1.f : p0;
            float a1 = (e1 == we) ? -1.f : p1;
            float wp2; int we2;
            if (a1 > a0) { wp2 = a1; we2 = e1; } else { wp2 = a0; we2 = e0; }
#pragma unroll
            for (int o = 16; o > 0; o >>= 1) {
                float op = __shfl_xor_sync(0xffffffffu, wp2, o);
                int   oe = __shfl_xor_sync(0xffffffffu, we2, o);
                if (op > wp2 || (op == wp2 && oe < we2)) { wp2 = op; we2 = oe; }
            }
            if (lane == 0) {
                g_gate[T0 + r] = make_float2(wp, wp2);
                g_eidx[T0 + r] = make_int2(we, we2);
                se[r]      = (unsigned char)we;
                se[64 + r] = (unsigned char)we2;
            }
        }
    }
    __syncthreads();

    // ---- block-local rank scan for both slots (warps 0 and 1) ----
    if (tid < 128) cntl[tid] = 0;
    __syncthreads();
    if ((tid >> 5) < 2) {
        const int slot = tid >> 5;
#pragma unroll
        for (int it = 0; it < 2; ++it) {
            int t = it*32 + lane;
            int e = se[slot*64 + t];
            unsigned mask = __match_any_sync(0xffffffffu, e);
            int rank = __popc(mask & ((1u << lane) - 1u));
            int base = cntl[slot*64 + e];
            lpos[slot*64 + t] = (unsigned char)(base + rank);
            __syncwarp();
            if (rank == 0) cntl[slot*64 + e] = base + __popc(mask);
            __syncwarp();
        }
    }
    __syncthreads();

    const int gidx = T0 >> 11;              // group = T0 / Sn
    const int blk  = (T0 & (Sn - 1)) >> 6;  // 64-token block within group
    if (tid < 128) {
        int k = tid >> 6, e = tid & 63;
        g_cnt[((gidx*2 + k)*32 + blk)*En + e] = cntl[k*64 + e];
    }
    if (tid < 64)
        g_lpos[T0 + tid] = make_uchar2(lpos[tid], lpos[64 + tid]);
}

// ===== K3: 64 CTAs: smem-staged per-expert prefix over blocks + scatter =====
__global__ void __launch_bounds__(256)
k3_scatter(float* __restrict__ out, long long out_n,
           const int* __restrict__ capp, int has_mask)
{
    __shared__ int scnt[32*En];   // all 32 block-count vectors for this (g,k)
    __shared__ int base[4][En];

    const int gk = blockIdx.x >> 3, q = blockIdx.x & 7;
    const int g = gk >> 1, k = gk & 1;
    const int tid = threadIdx.x;
    int cap = 64;
    if (capp) { cap = capp[0]; if (cap > 64) cap = 64; }

    // stage counts via coalesced loads
#pragma unroll
    for (int i = 0; i < 8; ++i)
        scnt[tid + 256*i] = g_cnt[gk*32*En + tid + 256*i];
    __syncthreads();

    // per-expert prefix over blocks (LDS chain)
    if (tid < En) {
        int acc = 0;
        const int e = tid;
        const int bend = q*4 + 4;
        for (int bq = 0; bq < bend; ++bq) {
            if (bq >= q*4) base[bq - q*4][e] = acc;
            acc += scnt[bq*En + e];
        }
    }
    __syncthreads();

    int sl = q*256 + tid;          // position within group
    int t  = g*Sn + sl;
    int2   ei = g_eidx[t];
    float2 gg = g_gate[t];
    uchar2 lp = g_lpos[t];
    int   e    = k ? ei.y : ei.x;
    float gate = k ? gg.y : gg.x;
    int   pos0 = base[(sl >> 6) & 3][e] + (int)(k ? lp.y : lp.x);
    if (pos0 + 1 < cap) {
        long long off = ((long long)t*En + e)*63 + pos0;
        if (off < out_n) out[off] = gate;
        if (has_mask) {
            long long moff = NCOMB + off;
            if (moff < out_n) out[moff] = (gate != 0.f) ? 1.f : 0.f;
        }
    }
}

// ================= launch =================
extern "C" void kernel_launch(void* const* d_in, const int* in_sizes, int n_in,
                              void* d_out, int out_size)
{
    const float* x = (const float*)d_in[0];
    const float* W = (const float*)d_in[1];
    const float* b = (const float*)d_in[2];
    const int* capp = (n_in >= 4) ? (const int*)d_in[3] : nullptr;
    float* out = (float*)d_out;
    long long out_n = (long long)out_size;
    int has_mask = (out_n >= 2LL*NCOMB) ? 1 : 0;

    cudaFuncSetAttribute(k1_fused, cudaFuncAttributeMaxDynamicSharedMemorySize, SMEM_K1);
    k1_fused<<<K1_BLOCKS, K1_THREADS, SMEM_K1>>>(x, W, b, out, out_n);
    k3_scatter<<<64, 256>>>(out, out_n, capp, has_mask);
}